// round 15
// baseline (speedup 1.0000x reference)
#include <cuda_runtime.h>
#include <cuda_fp16.h>
#include <cstdint>
#include <cstddef>

// Problem constants
#define BATCH 4
#define HEADS 16
#define LQ 2048
#define SK 2048
#define DH 64

// Tiling
#define BQ   32      // query rows per CTA (two 16-row halves)
#define SKT  128     // s-columns per iteration; each WARP owns 16 (8 col-groups x 2 halves)
#define NIT  (SK / SKT)
#define KPS  68      // padded stride Q tile (f32)
#define KHS  72      // K tile stride in halfs (64 + 8 pad) -> conflict-free frags
#define VTS  24      // Vt tile stride in halfs (16 + 8 pad) -> conflict-free frags
#define OSS  65      // padded stride O scratch

#define NTHREADS 512
#define NWARPS   16
#define NBUF     2

// per-warp buffer (halfs): K 16 x KHS + Vt 64 x VTS
#define KTILE_H  (16 * KHS)              // 1152
#define VTILE_H  (DH * VTS)              // 1536
#define WKV_H    (KTILE_H + VTILE_H)     // 2688 halfs (5376 B, 16B multiple)
#define WBLK_H   (NBUF * WKV_H)          // 5376 halfs per warp

// fp16 scratch copies of K (natural [bh][s][d]) and V (transposed [bh][d][s])
__device__ __half KH[(size_t)BATCH * HEADS * SK * DH];
__device__ __half VT[(size_t)BATCH * HEADS * DH * SK];

__device__ __forceinline__ uint32_t h2pack(float a, float b) {
    __half2 h = __floats2half2_rn(a, b);
    return *(uint32_t*)&h;
}

__device__ __forceinline__ void mma_f16_k16(float c[4], const uint32_t a[4], const uint32_t b[2]) {
    asm volatile(
        "mma.sync.aligned.m16n8k16.row.col.f32.f16.f16.f32 "
        "{%0,%1,%2,%3}, {%4,%5,%6,%7}, {%8,%9}, {%0,%1,%2,%3};"
        : "+f"(c[0]), "+f"(c[1]), "+f"(c[2]), "+f"(c[3])
        : "r"(a[0]), "r"(a[1]), "r"(a[2]), "r"(a[3]),
          "r"(b[0]), "r"(b[1]));
}

// ---- cp.async helpers ----
__device__ __forceinline__ void cp16(uint32_t smem_dst, const void* gsrc) {
    asm volatile("cp.async.cg.shared.global [%0], [%1], 16;\n"
                 :: "r"(smem_dst), "l"(gsrc));
}
__device__ __forceinline__ void cp_commit() {
    asm volatile("cp.async.commit_group;\n");
}
__device__ __forceinline__ void cp_wait1() {
    asm volatile("cp.async.wait_group 1;\n");
}

// ---- packed f32x2 helpers (FMA-pipe exp path) ----
__device__ __forceinline__ unsigned long long pk2(float a, float b) {
    unsigned long long r;
    asm("mov.b64 %0, {%1,%2};" : "=l"(r) : "f"(a), "f"(b));
    return r;
}
__device__ __forceinline__ void upk2(unsigned long long p, float& a, float& b) {
    asm("mov.b64 {%0,%1}, %2;" : "=f"(a), "=f"(b) : "l"(p));
}
__device__ __forceinline__ unsigned long long fma2(unsigned long long a,
                                                   unsigned long long b,
                                                   unsigned long long c) {
    unsigned long long d;
    asm("fma.rn.f32x2 %0, %1, %2, %3;" : "=l"(d) : "l"(a), "l"(b), "l"(c));
    return d;
}
__device__ __forceinline__ float ex2(float x) {
    float y;
    asm("ex2.approx.f32 %0, %1;" : "=f"(y) : "f"(x));
    return y;
}

// exp(x*0.125) for a pair, entirely on fma+alu pipes (deg-4, rel err ~4e-5).
__device__ __forceinline__ void exp8_pair(float x0, float x1, float& e0, float& e1) {
    const float KKf  = 0.18033688011112042f;   // 0.125 * log2(e)
    const float RNDf = 12582912.0f;            // 2^23 + 2^22
    unsigned long long K2   = pk2(KKf, KKf);
    unsigned long long RND2 = pk2(RNDf, RNDf);
    unsigned long long N1   = pk2(-1.0f, -1.0f);
    unsigned long long C4   = pk2(0.009618127f, 0.009618127f);
    unsigned long long C3   = pk2(0.055504109f, 0.055504109f);
    unsigned long long C2   = pk2(0.240226507f, 0.240226507f);
    unsigned long long C1   = pk2(0.693147181f, 0.693147181f);
    unsigned long long ONE  = pk2(1.0f, 1.0f);

    unsigned long long X = pk2(x0, x1);
    unsigned long long T = fma2(X, K2, RND2);
    unsigned long long W = fma2(T, N1, RND2);
    unsigned long long R = fma2(X, K2, W);
    unsigned long long P = fma2(R, C4, C3);
    P = fma2(P, R, C2);
    P = fma2(P, R, C1);
    P = fma2(P, R, ONE);

    float t0, t1, p0, p1;
    upk2(T, t0, t1);
    upk2(P, p0, p1);
    e0 = __int_as_float(__float_as_int(p0) + (__float_as_int(t0) << 23));
    e1 = __int_as_float(__float_as_int(p1) + (__float_as_int(t1) << 23));
}

// ==================== pre-pass: K -> fp16, V -> fp16 transposed ====================
__global__ void conv_kv_kernel(const float* __restrict__ k, const float* __restrict__ v) {
    const size_t stride = (size_t)gridDim.x * blockDim.x;
    const size_t NK4 = (size_t)BATCH * HEADS * SK * DH / 4;
    for (size_t i = (size_t)blockIdx.x * blockDim.x + threadIdx.x; i < NK4; i += stride) {
        float4 f = ((const float4*)k)[i];
        uint32_t u0 = h2pack(f.x, f.y);
        uint32_t u1 = h2pack(f.z, f.w);
        ((uint2*)KH)[i] = make_uint2(u0, u1);
    }
    const size_t NV = (size_t)BATCH * HEADS * (SK / 8) * DH;
    for (size_t i = (size_t)blockIdx.x * blockDim.x + threadIdx.x; i < NV; i += stride) {
        int d  = (int)(i & (DH - 1));
        int sc = (int)((i >> 6) & (SK / 8 - 1));
        int bh = (int)(i >> 14);
        const float* vp = v + ((size_t)bh * SK + (size_t)sc * 8) * DH + d;
        __half hh[8];
#pragma unroll
        for (int j = 0; j < 8; j++) hh[j] = __float2half_rn(vp[(size_t)j * DH]);
        *(uint4*)(VT + ((size_t)bh * DH + d) * SK + (size_t)sc * 8) = *(uint4*)hh;
    }
}

__global__ __launch_bounds__(NTHREADS, 1)
void attn_f16_kernel(const float* __restrict__ q,
                     float* __restrict__ out) {
    extern __shared__ char smraw[];
    __half* smh  = (__half*)smraw;                         // warp K/V buffers
    float*  smf  = (float*)(smraw + NWARPS * WBLK_H * 2);  // f32 region

    const int tid  = threadIdx.x;
    const int lane = tid & 31;
    const int warp = tid >> 5;
    const int cg   = warp & 7;       // column group 0..7
    const int half = warp >> 3;      // 0: rows 0-15, 1: rows 16-31
    const int gr   = lane >> 2;      // 0..7
    const int tg   = lane & 3;       // 0..3

    __half* Wb  = smh + warp * WBLK_H;      // this warp's PRIVATE double buffer
    float* Qs  = smf;                       // [32][KPS]
    float* Os  = Qs + BQ * KPS;             // [32][OSS]
    float* red = Os + BQ * OSS;             // [32]
    float* inv = red + BQ;                  // [32]

    const int bh  = blockIdx.y;
    const int q0  = blockIdx.x * BQ;

    const float*  qp  = q + ((size_t)bh * LQ + q0) * DH;
    const __half* kph = KH + (size_t)bh * SK * DH;
    const __half* vth = VT + (size_t)bh * DH * SK;
    float* op = out + ((size_t)bh * LQ + q0) * DH;
    float* sp = out + (size_t)BATCH * HEADS * LQ * DH
                    + ((size_t)bh * LQ + q0) * (size_t)SK;

    // ---- zero scratch ----
    for (int i = tid; i < BQ * OSS; i += NTHREADS) Os[i] = 0.f;
    if (tid < BQ) red[tid] = 0.f;

    // ---- load Q tile (32 x 64) : one float4 per thread ----
    {
        int r = tid >> 4, c4 = tid & 15;
        *(float4*)(Qs + r * KPS + c4 * 4) =
            *(const float4*)(qp + (size_t)r * DH + c4 * 4);
    }
    __syncthreads();

    // ---- Q A-fragments (fp16) for this warp's 16-row half: 4 k16-steps x 4 regs ----
    const int r0 = half * 16;
    uint32_t qa[4][4];
#pragma unroll
    for (int m = 0; m < 4; m++) {
        const float* ra = Qs + (r0 + gr) * KPS + m * 16;
        const float* rb = Qs + (r0 + gr + 8) * KPS + m * 16;
        qa[m][0] = h2pack(ra[2 * tg],     ra[2 * tg + 1]);
        qa[m][1] = h2pack(rb[2 * tg],     rb[2 * tg + 1]);
        qa[m][2] = h2pack(ra[2 * tg + 8], ra[2 * tg + 9]);
        qa[m][3] = h2pack(rb[2 * tg + 8], rb[2 * tg + 9]);
    }

    // per-warp O accumulators: 16 rows x 64 cols (8 n-chunks of m16n8)
    float o[8][4];
#pragma unroll
    for (int j = 0; j < 8; j++) { o[j][0] = o[j][1] = o[j][2] = o[j][3] = 0.f; }

    float rs0 = 0.f, rs1 = 0.f;            // row-sum partials
    const int wc = cg * 16;                // warp's 16 columns within tile
    const float KKf = 0.18033688011112042f;

    const uint32_t wb_sh = (uint32_t)__cvta_generic_to_shared(Wb);

    // warp-private stage: BOTH K (16 s-rows x 64d) and Vt (64d x 16s)
    auto stage = [&](int b, int s0) {
        uint32_t kd = wb_sh + (uint32_t)(b * WKV_H) * 2u;
        const __half* kpt = kph + (size_t)(s0 + wc) * DH;
#pragma unroll
        for (int i = 0; i < 4; i++) {
            int idx = lane + i * 32;        // 0..127
            int r = idx >> 3, c = idx & 7;  // row 0..15, 16B chunk 0..7
            cp16(kd + (uint32_t)(r * KHS * 2 + c * 16),
                 kpt + (size_t)r * DH + c * 8);
        }
        uint32_t vd = wb_sh + (uint32_t)(b * WKV_H + KTILE_H) * 2u;
        const __half* vpt = vth + (size_t)(s0 + wc);
#pragma unroll
        for (int i = 0; i < 4; i++) {
            int idx = lane + i * 32;        // 0..127
            int d = idx >> 1, c = idx & 1;  // d-row 0..63, 16B chunk 0..1
            cp16(vd + (uint32_t)(d * VTS * 2 + c * 16),
                 vpt + (size_t)d * SK + c * 8);
        }
    };

    // ============ barrier-free, warp-autonomous double-buffered loop ============
    stage(0, 0);
    cp_commit();

#pragma unroll 2
    for (int it = 0; it < NIT; it++) {
        if (it + 1 < NIT) stage((it + 1) & 1, (it + 1) * SKT);
        cp_commit();
        cp_wait1();          // my buffer `it` complete (prefetch in flight)
        __syncwarp();        // cross-lane visibility of staged data

        __half* Kw = Wb + (it & 1) * WKV_H;
        __half* Vw = Kw + KTILE_H;

        // --- QK^T: two independent chains of 4 x m16n8k16 ---
        float acc0[4] = {0.f, 0.f, 0.f, 0.f};
        float acc1[4] = {0.f, 0.f, 0.f, 0.f};
#pragma unroll
        for (int m = 0; m < 4; m++) {
            uint32_t b0[2], b1[2];
            b0[0] = *(const uint32_t*)(Kw + gr * KHS + m * 16 + 2 * tg);
            b0[1] = *(const uint32_t*)(Kw + gr * KHS + m * 16 + 2 * tg + 8);
            b1[0] = *(const uint32_t*)(Kw + (8 + gr) * KHS + m * 16 + 2 * tg);
            b1[1] = *(const uint32_t*)(Kw + (8 + gr) * KHS + m * 16 + 2 * tg + 8);
            mma_f16_k16(acc0, qa[m], b0);
            mma_f16_k16(acc1, qa[m], b1);
        }

        // --- exp: chunk0 fma-poly, chunk1 MUFU (split proven neutral) ---
        float e0, e1, e2, e3, f0, f1, f2, f3;
        exp8_pair(acc0[0], acc0[1], e0, e1);
        exp8_pair(acc0[2], acc0[3], e2, e3);
        f0 = ex2(acc1[0] * KKf);
        f1 = ex2(acc1[1] * KKf);
        f2 = ex2(acc1[2] * KKf);
        f3 = ex2(acc1[3] * KKf);

        rs0 += (e0 + e1) + (f0 + f1);
        rs1 += (e2 + e3) + (f2 + f3);

        // --- write unnormalized scores straight to GMEM ---
        {
            int gcol = it * SKT + wc + 2 * tg;
            *(float2*)(sp + (size_t)(r0 + gr) * SK + gcol)         = make_float2(e0, e1);
            *(float2*)(sp + (size_t)(r0 + gr + 8) * SK + gcol)     = make_float2(e2, e3);
            *(float2*)(sp + (size_t)(r0 + gr) * SK + gcol + 8)     = make_float2(f0, f1);
            *(float2*)(sp + (size_t)(r0 + gr + 8) * SK + gcol + 8) = make_float2(f2, f3);
        }

        // --- PV A-fragment (k16) = concatenated C-fragments, packed ---
        uint32_t a[4];
        a[0] = h2pack(e0, e1);   // row gr,   k = 2tg,2tg+1
        a[1] = h2pack(e2, e3);   // row gr+8, k = 2tg,2tg+1
        a[2] = h2pack(f0, f1);   // row gr,   k = 8+2tg
        a[3] = h2pack(f2, f3);   // row gr+8, k = 8+2tg

        // --- PV: O += E_chunk(16x16) @ V(16x64); 8 independent k16 MMAs ---
#pragma unroll
        for (int j = 0; j < 8; j++) {
            uint32_t b[2];
            b[0] = *(const uint32_t*)(Vw + (j * 8 + gr) * VTS + 2 * tg);
            b[1] = *(const uint32_t*)(Vw + (j * 8 + gr) * VTS + 8 + 2 * tg);
            mma_f16_k16(o[j], a, b);
        }
    }

    // ==================== reductions ====================
    rs0 += __shfl_xor_sync(0xffffffffu, rs0, 1);
    rs0 += __shfl_xor_sync(0xffffffffu, rs0, 2);
    rs1 += __shfl_xor_sync(0xffffffffu, rs1, 1);
    rs1 += __shfl_xor_sync(0xffffffffu, rs1, 2);
    if (tg == 0) {
        atomicAdd(&red[r0 + gr], rs0);
        atomicAdd(&red[r0 + gr + 8], rs1);
    }
#pragma unroll
    for (int j = 0; j < 8; j++) {
        int c = j * 8 + 2 * tg;
        atomicAdd(&Os[(r0 + gr) * OSS + c],           o[j][0]);
        atomicAdd(&Os[(r0 + gr) * OSS + c + 1],       o[j][1]);
        atomicAdd(&Os[(r0 + gr + 8) * OSS + c],       o[j][2]);
        atomicAdd(&Os[(r0 + gr + 8) * OSS + c + 1],   o[j][3]);
    }
    __syncthreads();
    if (tid < BQ) inv[tid] = 1.0f / red[tid];
    __syncthreads();

    // ==================== normalize scores in-place (L2-resident) ====================
    {
#pragma unroll
        for (int i = 0; i < 32; i++) {
            int idx = tid + i * NTHREADS;     // float4 index within 32x2048
            int r  = idx >> 9;                // 512 float4 per row
            int c4 = idx & 511;
            float4 e = *(float4*)(sp + (size_t)r * SK + c4 * 4);
            float is = inv[r];
            e.x *= is; e.y *= is; e.z *= is; e.w *= is;
            *(float4*)(sp + (size_t)r * SK + c4 * 4) = e;
        }
    }

    // ==================== write O ====================
    {
#pragma unroll
        for (int i = 0; i < 4; i++) {
            int idx = tid + i * NTHREADS;     // 0..2047
            int r = idx >> 6, c = idx & 63;
            op[(size_t)r * DH + c] = Os[r * OSS + c] * inv[r];
        }
    }
}

extern "C" void kernel_launch(void* const* d_in, const int* in_sizes, int n_in,
                              void* d_out, int out_size) {
    const float* q = (const float*)d_in[0];
    const float* k = (const float*)d_in[1];
    const float* v = (const float*)d_in[2];
    float* out = (float*)d_out;

    // SMEM: warp buffers (halfs) + f32 region (Q, Os, red, inv)
    size_t smem = (size_t)(NWARPS * WBLK_H) * 2
                + (size_t)(BQ * KPS + BQ * OSS + 2 * BQ) * 4;

    static bool configured = false;
    if (!configured) {
        cudaFuncSetAttribute(attn_f16_kernel,
                             cudaFuncAttributeMaxDynamicSharedMemorySize,
                             (int)smem);
        configured = true;
    }

    conv_kv_kernel<<<2048, 256>>>(k, v);

    dim3 grid(LQ / BQ, BATCH * HEADS);   // (64, 64)
    attn_f16_kernel<<<grid, NTHREADS, smem>>>(q, out);
}

// round 16
// speedup vs baseline: 1.4298x; 1.4298x over previous
#include <cuda_runtime.h>
#include <cuda_fp16.h>
#include <cstdint>
#include <cstddef>

// Problem constants
#define BATCH 4
#define HEADS 16
#define LQ 2048
#define SK 2048
#define DH 64

// Tiling
#define BQ   32      // query rows per CTA (two 16-row halves, warp-paired)
#define SKT  64      // s-columns per iteration; each PAIR owns 16
#define NIT  (SK / SKT)
#define KPS  68      // padded stride Q tile (f32)
#define KHS  72      // K tile stride in halfs (64 + 8 pad) -> conflict-free frags
#define VTS  24      // Vt tile stride in halfs (16 + 8 pad) -> conflict-free frags
#define OSS  65      // padded stride O scratch

#define NTHREADS 256
#define NWARPS   8
#define NPAIRS   4
#define NBUF     2

// per-pair buffer (halfs): K 16 x KHS + Vt 64 x VTS
#define KTILE_H  (16 * KHS)              // 1152
#define VTILE_H  (DH * VTS)              // 1536
#define WKV_H    (KTILE_H + VTILE_H)     // 2688 halfs (5376 B, 16B multiple)
#define WBLK_H   (NBUF * WKV_H)          // 5376 halfs per pair

// fp16 scratch copies of K (natural [bh][s][d]) and V (transposed [bh][d][s])
__device__ __half KH[(size_t)BATCH * HEADS * SK * DH];
__device__ __half VT[(size_t)BATCH * HEADS * DH * SK];

__device__ __forceinline__ uint32_t h2pack(float a, float b) {
    __half2 h = __floats2half2_rn(a, b);
    return *(uint32_t*)&h;
}

__device__ __forceinline__ void mma_f16_k16(float c[4], const uint32_t a[4], const uint32_t b[2]) {
    asm volatile(
        "mma.sync.aligned.m16n8k16.row.col.f32.f16.f16.f32 "
        "{%0,%1,%2,%3}, {%4,%5,%6,%7}, {%8,%9}, {%0,%1,%2,%3};"
        : "+f"(c[0]), "+f"(c[1]), "+f"(c[2]), "+f"(c[3])
        : "r"(a[0]), "r"(a[1]), "r"(a[2]), "r"(a[3]),
          "r"(b[0]), "r"(b[1]));
}

// ---- cp.async helpers ----
__device__ __forceinline__ void cp16(uint32_t smem_dst, const void* gsrc) {
    asm volatile("cp.async.cg.shared.global [%0], [%1], 16;\n"
                 :: "r"(smem_dst), "l"(gsrc));
}
__device__ __forceinline__ void cp_commit() {
    asm volatile("cp.async.commit_group;\n");
}
__device__ __forceinline__ void cp_wait1() {
    asm volatile("cp.async.wait_group 1;\n");
}
__device__ __forceinline__ void pair_bar(int id) {
    asm volatile("bar.sync %0, 64;" :: "r"(id) : "memory");
}

// ---- packed f32x2 helpers (FMA-pipe exp path) ----
__device__ __forceinline__ unsigned long long pk2(float a, float b) {
    unsigned long long r;
    asm("mov.b64 %0, {%1,%2};" : "=l"(r) : "f"(a), "f"(b));
    return r;
}
__device__ __forceinline__ void upk2(unsigned long long p, float& a, float& b) {
    asm("mov.b64 {%0,%1}, %2;" : "=f"(a), "=f"(b) : "l"(p));
}
__device__ __forceinline__ unsigned long long fma2(unsigned long long a,
                                                   unsigned long long b,
                                                   unsigned long long c) {
    unsigned long long d;
    asm("fma.rn.f32x2 %0, %1, %2, %3;" : "=l"(d) : "l"(a), "l"(b), "l"(c));
    return d;
}
__device__ __forceinline__ float ex2(float x) {
    float y;
    asm("ex2.approx.f32 %0, %1;" : "=f"(y) : "f"(x));
    return y;
}

// exp(x*0.125) for a pair, entirely on fma+alu pipes (deg-4, rel err ~4e-5).
__device__ __forceinline__ void exp8_pair(float x0, float x1, float& e0, float& e1) {
    const float KKf  = 0.18033688011112042f;   // 0.125 * log2(e)
    const float RNDf = 12582912.0f;            // 2^23 + 2^22
    unsigned long long K2   = pk2(KKf, KKf);
    unsigned long long RND2 = pk2(RNDf, RNDf);
    unsigned long long N1   = pk2(-1.0f, -1.0f);
    unsigned long long C4   = pk2(0.009618127f, 0.009618127f);
    unsigned long long C3   = pk2(0.055504109f, 0.055504109f);
    unsigned long long C2   = pk2(0.240226507f, 0.240226507f);
    unsigned long long C1   = pk2(0.693147181f, 0.693147181f);
    unsigned long long ONE  = pk2(1.0f, 1.0f);

    unsigned long long X = pk2(x0, x1);
    unsigned long long T = fma2(X, K2, RND2);
    unsigned long long W = fma2(T, N1, RND2);
    unsigned long long R = fma2(X, K2, W);
    unsigned long long P = fma2(R, C4, C3);
    P = fma2(P, R, C2);
    P = fma2(P, R, C1);
    P = fma2(P, R, ONE);

    float t0, t1, p0, p1;
    upk2(T, t0, t1);
    upk2(P, p0, p1);
    e0 = __int_as_float(__float_as_int(p0) + (__float_as_int(t0) << 23));
    e1 = __int_as_float(__float_as_int(p1) + (__float_as_int(t1) << 23));
}

// ==================== pre-pass: K -> fp16, V -> fp16 transposed ====================
__global__ void conv_kv_kernel(const float* __restrict__ k, const float* __restrict__ v) {
    const size_t stride = (size_t)gridDim.x * blockDim.x;
    const size_t NK4 = (size_t)BATCH * HEADS * SK * DH / 4;
    for (size_t i = (size_t)blockIdx.x * blockDim.x + threadIdx.x; i < NK4; i += stride) {
        float4 f = ((const float4*)k)[i];
        uint32_t u0 = h2pack(f.x, f.y);
        uint32_t u1 = h2pack(f.z, f.w);
        ((uint2*)KH)[i] = make_uint2(u0, u1);
    }
    const size_t NV = (size_t)BATCH * HEADS * (SK / 8) * DH;
    for (size_t i = (size_t)blockIdx.x * blockDim.x + threadIdx.x; i < NV; i += stride) {
        int d  = (int)(i & (DH - 1));
        int sc = (int)((i >> 6) & (SK / 8 - 1));
        int bh = (int)(i >> 14);
        const float* vp = v + ((size_t)bh * SK + (size_t)sc * 8) * DH + d;
        __half hh[8];
#pragma unroll
        for (int j = 0; j < 8; j++) hh[j] = __float2half_rn(vp[(size_t)j * DH]);
        *(uint4*)(VT + ((size_t)bh * DH + d) * SK + (size_t)sc * 8) = *(uint4*)hh;
    }
}

__global__ __launch_bounds__(NTHREADS, 2)
void attn_f16_kernel(const float* __restrict__ q,
                     float* __restrict__ out) {
    extern __shared__ char smraw[];
    __half* smh  = (__half*)smraw;                         // pair K/V buffers
    float*  smf  = (float*)(smraw + NPAIRS * WBLK_H * 2);  // f32 region

    const int tid  = threadIdx.x;
    const int lane = tid & 31;
    const int warp = tid >> 5;
    const int pair = warp & 3;       // 0..3
    const int half = warp >> 2;      // 0: rows 0-15 & stages K; 1: rows 16-31 & stages V
    const int gr   = lane >> 2;      // 0..7
    const int tg   = lane & 3;       // 0..3

    __half* Pb  = smh + pair * WBLK_H;      // this pair's double buffer
    float* Qs  = smf;                       // [32][KPS]
    float* Os  = Qs + BQ * KPS;             // [32][OSS]
    float* red = Os + BQ * OSS;             // [32]
    float* inv = red + BQ;                  // [32]

    const int bh  = blockIdx.y;
    const int q0  = blockIdx.x * BQ;

    const float*  qp  = q + ((size_t)bh * LQ + q0) * DH;
    const __half* kph = KH + (size_t)bh * SK * DH;
    const __half* vth = VT + (size_t)bh * DH * SK;
    float* op = out + ((size_t)bh * LQ + q0) * DH;
    float* sp = out + (size_t)BATCH * HEADS * LQ * DH
                    + ((size_t)bh * LQ + q0) * (size_t)SK;

    // ---- zero scratch ----
    for (int i = tid; i < BQ * OSS; i += NTHREADS) Os[i] = 0.f;
    if (tid < BQ) red[tid] = 0.f;

    // ---- load Q tile (32 x 64) : two float4 per thread ----
    {
#pragma unroll
        for (int i = 0; i < 2; i++) {
            int idx = tid + i * NTHREADS;
            int r = idx >> 4, c4 = idx & 15;
            *(float4*)(Qs + r * KPS + c4 * 4) =
                *(const float4*)(qp + (size_t)r * DH + c4 * 4);
        }
    }
    __syncthreads();

    // ---- Q A-fragments (fp16) for this warp's 16-row half: 4 k16-steps x 4 regs ----
    const int r0 = half * 16;
    uint32_t qa[4][4];
#pragma unroll
    for (int m = 0; m < 4; m++) {
        const float* ra = Qs + (r0 + gr) * KPS + m * 16;
        const float* rb = Qs + (r0 + gr + 8) * KPS + m * 16;
        qa[m][0] = h2pack(ra[2 * tg],     ra[2 * tg + 1]);
        qa[m][1] = h2pack(rb[2 * tg],     rb[2 * tg + 1]);
        qa[m][2] = h2pack(ra[2 * tg + 8], ra[2 * tg + 9]);
        qa[m][3] = h2pack(rb[2 * tg + 8], rb[2 * tg + 9]);
    }

    // per-warp O accumulators: 16 rows x 64 cols (8 n-chunks of m16n8)
    float o[8][4];
#pragma unroll
    for (int j = 0; j < 8; j++) { o[j][0] = o[j][1] = o[j][2] = o[j][3] = 0.f; }

    float rs0 = 0.f, rs1 = 0.f;            // row-sum partials
    const int wc = pair * 16;              // pair's 16 columns within tile
    const float KKf = 0.18033688011112042f;
    const int barid = pair + 1;            // named barriers 1..4

    const uint32_t pb_sh = (uint32_t)__cvta_generic_to_shared(Pb);

    // stage one half: half 0 stages K (16 s-rows x 64d), half 1 stages Vt (64d x 16s)
    auto stage = [&](int b, int s0) {
        if (half == 0) {
            uint32_t kd = pb_sh + (uint32_t)(b * WKV_H) * 2u;
            const __half* kpt = kph + (size_t)(s0 + wc) * DH;
#pragma unroll
            for (int i = 0; i < 4; i++) {
                int idx = lane + i * 32;        // 0..127
                int r = idx >> 3, c = idx & 7;  // row 0..15, 16B chunk 0..7
                cp16(kd + (uint32_t)(r * KHS * 2 + c * 16),
                     kpt + (size_t)r * DH + c * 8);
            }
        } else {
            uint32_t vd = pb_sh + (uint32_t)(b * WKV_H + KTILE_H) * 2u;
            const __half* vpt = vth + (size_t)(s0 + wc);
#pragma unroll
            for (int i = 0; i < 4; i++) {
                int idx = lane + i * 32;        // 0..127
                int d = idx >> 1, c = idx & 1;  // d-row 0..63, 16B chunk 0..1
                cp16(vd + (uint32_t)(d * VTS * 2 + c * 16),
                     vpt + (size_t)d * SK + c * 8);
            }
        }
    };

    // ============ pipeline: stage -> commit -> wait1 -> bar (R14-proven) ============
    stage(0, 0);
    cp_commit();

#pragma unroll 2
    for (int it = 0; it < NIT; it++) {
        if (it + 1 < NIT) stage((it + 1) & 1, (it + 1) * SKT);
        cp_commit();
        cp_wait1();          // my half of buffer `it` complete
        pair_bar(barid);     // partner's half complete + visible

        __half* Kw = Pb + (it & 1) * WKV_H;
        __half* Vw = Kw + KTILE_H;

        // --- QK^T: two independent chains of 4 x m16n8k16 ---
        float acc0[4] = {0.f, 0.f, 0.f, 0.f};
        float acc1[4] = {0.f, 0.f, 0.f, 0.f};
#pragma unroll
        for (int m = 0; m < 4; m++) {
            uint32_t b0[2], b1[2];
            b0[0] = *(const uint32_t*)(Kw + gr * KHS + m * 16 + 2 * tg);
            b0[1] = *(const uint32_t*)(Kw + gr * KHS + m * 16 + 2 * tg + 8);
            b1[0] = *(const uint32_t*)(Kw + (8 + gr) * KHS + m * 16 + 2 * tg);
            b1[1] = *(const uint32_t*)(Kw + (8 + gr) * KHS + m * 16 + 2 * tg + 8);
            mma_f16_k16(acc0, qa[m], b0);
            mma_f16_k16(acc1, qa[m], b1);
        }

        // --- exp: chunk0 fma-poly, chunk1 MUFU (50/50; split proven neutral) ---
        float e0, e1, e2, e3, f0, f1, f2, f3;
        exp8_pair(acc0[0], acc0[1], e0, e1);
        exp8_pair(acc0[2], acc0[3], e2, e3);
        f0 = ex2(acc1[0] * KKf);
        f1 = ex2(acc1[1] * KKf);
        f2 = ex2(acc1[2] * KKf);
        f3 = ex2(acc1[3] * KKf);

        rs0 += (e0 + e1) + (f0 + f1);
        rs1 += (e2 + e3) + (f2 + f3);

        // --- write unnormalized scores straight to GMEM ---
        {
            int gcol = it * SKT + wc + 2 * tg;
            *(float2*)(sp + (size_t)(r0 + gr) * SK + gcol)         = make_float2(e0, e1);
            *(float2*)(sp + (size_t)(r0 + gr + 8) * SK + gcol)     = make_float2(e2, e3);
            *(float2*)(sp + (size_t)(r0 + gr) * SK + gcol + 8)     = make_float2(f0, f1);
            *(float2*)(sp + (size_t)(r0 + gr + 8) * SK + gcol + 8) = make_float2(f2, f3);
        }

        // --- PV A-fragment (k16) = concatenated C-fragments, packed ---
        uint32_t a[4];
        a[0] = h2pack(e0, e1);   // row gr,   k = 2tg,2tg+1
        a[1] = h2pack(e2, e3);   // row gr+8, k = 2tg,2tg+1
        a[2] = h2pack(f0, f1);   // row gr,   k = 8+2tg
        a[3] = h2pack(f2, f3);   // row gr+8, k = 8+2tg

        // --- PV: O += E_chunk(16x16) @ V(16x64); 8 independent k16 MMAs ---
#pragma unroll
        for (int j = 0; j < 8; j++) {
            uint32_t b[2];
            b[0] = *(const uint32_t*)(Vw + (j * 8 + gr) * VTS + 2 * tg);
            b[1] = *(const uint32_t*)(Vw + (j * 8 + gr) * VTS + 8 + 2 * tg);
            mma_f16_k16(o[j], a, b);
        }

        pair_bar(barid);     // partner done reading buffer `it` (WAR for next stage)
    }

    // ==================== reductions ====================
    rs0 += __shfl_xor_sync(0xffffffffu, rs0, 1);
    rs0 += __shfl_xor_sync(0xffffffffu, rs0, 2);
    rs1 += __shfl_xor_sync(0xffffffffu, rs1, 1);
    rs1 += __shfl_xor_sync(0xffffffffu, rs1, 2);
    if (tg == 0) {
        atomicAdd(&red[r0 + gr], rs0);
        atomicAdd(&red[r0 + gr + 8], rs1);
    }
#pragma unroll
    for (int j = 0; j < 8; j++) {
        int c = j * 8 + 2 * tg;
        atomicAdd(&Os[(r0 + gr) * OSS + c],           o[j][0]);
        atomicAdd(&Os[(r0 + gr) * OSS + c + 1],       o[j][1]);
        atomicAdd(&Os[(r0 + gr + 8) * OSS + c],       o[j][2]);
        atomicAdd(&Os[(r0 + gr + 8) * OSS + c + 1],   o[j][3]);
    }
    __syncthreads();
    if (tid < BQ) inv[tid] = 1.0f / red[tid];
    __syncthreads();

    // ==================== normalize scores in-place (L2-resident) ====================
    {
#pragma unroll
        for (int i = 0; i < 64; i++) {
            int idx = tid + i * NTHREADS;     // float4 index within 32x2048
            int r  = idx >> 9;                // 512 float4 per row
            int c4 = idx & 511;
            float4 e = *(float4*)(sp + (size_t)r * SK + c4 * 4);
            float is = inv[r];
            e.x *= is; e.y *= is; e.z *= is; e.w *= is;
            *(float4*)(sp + (size_t)r * SK + c4 * 4) = e;
        }
    }

    // ==================== write O ====================
    {
#pragma unroll
        for (int i = 0; i < 8; i++) {
            int idx = tid + i * NTHREADS;     // 0..2047
            int r = idx >> 6, c = idx & 63;
            op[(size_t)r * DH + c] = Os[r * OSS + c] * inv[r];
        }
    }
}

extern "C" void kernel_launch(void* const* d_in, const int* in_sizes, int n_in,
                              void* d_out, int out_size) {
    const float* q = (const float*)d_in[0];
    const float* k = (const float*)d_in[1];
    const float* v = (const float*)d_in[2];
    float* out = (float*)d_out;

    // SMEM: pair buffers (halfs) + f32 region (Q, Os, red, inv)
    size_t smem = (size_t)(NPAIRS * WBLK_H) * 2
                + (size_t)(BQ * KPS + BQ * OSS + 2 * BQ) * 4;

    static bool configured = false;
    if (!configured) {
        cudaFuncSetAttribute(attn_f16_kernel,
                             cudaFuncAttributeMaxDynamicSharedMemorySize,
                             (int)smem);
        configured = true;
    }

    conv_kv_kernel<<<2048, 256>>>(k, v);

    dim3 grid(LQ / BQ, BATCH * HEADS);   // (64, 64)
    attn_f16_kernel<<<grid, NTHREADS, smem>>>(q, out);
}